// round 16
// baseline (speedup 1.0000x reference)
#include <cuda_runtime.h>
#include <cuda_fp16.h>
#include <math.h>

#define NN 131072
#define NE 2097152
#define NG 512

// ---------------- scratch (device globals; no runtime allocation) ----------------
__device__ float  g_xl[NN * 128];     // reinterpreted as __half (head-paired layout)
__device__ float  g_xr[NN * 128];
__device__ float  g_agg[NN * 64];
__device__ float  g_pool[NG * 64];
__device__ float  g_z[NG * 32];
__device__ double g_bns[128];
__device__ double g_bns3[64];
__device__ int    g_rowptr[NN + 1];
__device__ int    g_cnt[NN];
__device__ int    g_cursor[NN];
__device__ float4 g_eas[NE];     // (a0,a1,a2, bitcast src)
__device__ int    g_bsum[128];
__device__ int    g_gstart[NG + 1];

// ---------------- degree count ----------------
__global__ void k_count(const int* __restrict__ ei, int* cnt) {
    int e = blockIdx.x * blockDim.x + threadIdx.x;
    if (e >= NE) return;
    atomicAdd(&cnt[ei[NE + e]], 1);
}

// ---------------- CSR scan (3-phase) ----------------
__global__ void k_scan1(const int* __restrict__ cnt, int* rowptr, int* bsum) {
    __shared__ int sh[1024];
    int t = threadIdx.x;
    int i = blockIdx.x * 1024 + t;
    int v = cnt[i];
    sh[t] = v;
    __syncthreads();
    for (int off = 1; off < 1024; off <<= 1) {
        int u = (t >= off) ? sh[t - off] : 0;
        __syncthreads();
        sh[t] += u;
        __syncthreads();
    }
    rowptr[i] = sh[t] - v;   // exclusive
    if (t == 1023) bsum[blockIdx.x] = sh[1023];
}

__global__ void k_scan2(int* bsum) {
    __shared__ int sh[128];
    int t = threadIdx.x;
    int orig = bsum[t];
    sh[t] = orig;
    __syncthreads();
    for (int off = 1; off < 128; off <<= 1) {
        int u = (t >= off) ? sh[t - off] : 0;
        __syncthreads();
        sh[t] += u;
        __syncthreads();
    }
    bsum[t] = sh[t] - orig;  // exclusive
}

__global__ void k_scan3(int* rowptr, const int* __restrict__ bsum, int* cursor) {
    int i = blockIdx.x * blockDim.x + threadIdx.x;
    if (i >= NN) {
        if (i == NN) rowptr[NN] = NE;   // sentinel
        return;
    }
    int r = rowptr[i] + bsum[i >> 10];
    rowptr[i] = r;
    cursor[i] = r;
}

__global__ void k_scatter(const int* __restrict__ ei, const float* __restrict__ ea,
                          int* cursor, float4* eas) {
    int e = blockIdx.x * blockDim.x + threadIdx.x;
    if (e >= NE) return;
    int dst = ei[NE + e];
    int pos = atomicAdd(&cursor[dst], 1);
    eas[pos] = make_float4(ea[e * 3 + 0], ea[e * 3 + 1], ea[e * 3 + 2],
                           __int_as_float(ei[e]));
}

// ---------------- graph boundaries (batch is sorted) ----------------
__global__ void k_bounds(const int* __restrict__ batch, int* gstart) {
    int g = blockIdx.x * blockDim.x + threadIdx.x;
    if (g > NG) return;
    int lo = 0, hi = NN;
    while (lo < hi) {
        int mid = (lo + hi) >> 1;
        if (batch[mid] < g) lo = mid + 1; else hi = mid;
    }
    gstart[g] = lo;
}

// ---------------- register-tiled node linear ----------------
// xl output (blockIdx.y==0) stored as fp16 head-paired: h[node*BN + 2*(c%C) + c/C]
template <int K, int BN, int TN, bool BNELU>
__global__ void k_lin(const float* __restrict__ in,
                      const float* __restrict__ wl, const float* __restrict__ bl,
                      const float* __restrict__ wr, const float* __restrict__ br,
                      const float* __restrict__ bias, const double* __restrict__ bns,
                      const float* __restrict__ gam, const float* __restrict__ bet,
                      __half* __restrict__ xlh, float* __restrict__ xr) {
    const int BM = 64, TM = 4;
    const int C = BN / 2;
    __shared__ float sx[BM][K + 1];
    __shared__ float sw[K * BN];
    __shared__ float ss[K], st[K];
    const float* w  = blockIdx.y ? wr : wl;
    const float* bb = blockIdx.y ? br : bl;
    int tid = threadIdx.x;

    for (int i = tid; i < K * BN; i += 256) sw[i] = w[i];
    if (BNELU && tid < K) {
        double mu = bns[tid] / (double)NN;
        double var = bns[K + tid] / (double)NN - mu * mu;
        float rs = rsqrtf((float)var + 1e-5f);
        ss[tid] = rs * gam[tid];
        st[tid] = (bias[tid] - (float)mu) * rs * gam[tid] + bet[tid];
    }
    int node0 = blockIdx.x * BM;
    for (int i = tid; i < BM * K; i += 256) {
        int r = i / K, c = i % K;
        sx[r][c] = in[(size_t)(node0 + r) * K + c];
    }
    __syncthreads();
    if (BNELU) {
        for (int i = tid; i < BM * K; i += 256) {
            int r = i / K, c = i % K;
            float v = sx[r][c] * ss[c] + st[c];
            sx[r][c] = (v > 0.0f) ? v : expm1f(v);
        }
        __syncthreads();
    }

    int ty = tid / 16, tx = tid % 16;
    int nb = ty * TM, cb = tx * TN;
    float acc[TM][TN];
    #pragma unroll
    for (int m = 0; m < TM; m++)
        #pragma unroll
        for (int n = 0; n < TN; n++) acc[m][n] = bb[cb + n];

    #pragma unroll 4
    for (int k = 0; k < K; k++) {
        float a[TM], b[TN];
        #pragma unroll
        for (int m = 0; m < TM; m++) a[m] = sx[nb + m][k];
        #pragma unroll
        for (int n = 0; n < TN; n += 4) {
            float4 v = *(const float4*)&sw[k * BN + cb + n];
            b[n] = v.x; b[n + 1] = v.y; b[n + 2] = v.z; b[n + 3] = v.w;
        }
        #pragma unroll
        for (int m = 0; m < TM; m++)
            #pragma unroll
            for (int n = 0; n < TN; n++) acc[m][n] += a[m] * b[n];
    }
    if (blockIdx.y == 0) {
        // xl: fp16 head-paired stores
        #pragma unroll
        for (int m = 0; m < TM; m++)
            #pragma unroll
            for (int n = 0; n < TN; n++) {
                int col = cb + n;
                int pc = (col < C) ? (2 * col) : (2 * (col - C) + 1);
                xlh[(size_t)(node0 + nb + m) * BN + pc] = __float2half(acc[m][n]);
            }
    } else {
        #pragma unroll
        for (int m = 0; m < TM; m++)
            #pragma unroll
            for (int n = 0; n < TN; n += 4) {
                float4 v = make_float4(acc[m][n], acc[m][n + 1], acc[m][n + 2], acc[m][n + 3]);
                *(float4*)&xr[(size_t)(node0 + nb + m) * BN + cb + n] = v;
            }
    }
}

// ---------------- fused GATv2 (half2 xl gathers, eas-prefetch pipeline) ----------------
template <int J>
__device__ __forceinline__ void gat_one(const __half2* __restrict__ xls,
                                        float a0, float a1, float a2, int lane,
                                        const float* rxr, const float* w0,
                                        const float* w1, const float* w2,
                                        const float* at, float* acc,
                                        float& m0, float& m1, float& s0, float& s1) {
    float rxl[J];
    #pragma unroll
    for (int jj = 0; jj < J / 2; jj++) {
        float2 f = __half22float2(xls[lane + 32 * jj]);
        rxl[jj] = f.x;
        rxl[jj + J / 2] = f.y;
    }
    float l0 = 0.0f, l1 = 0.0f;
    #pragma unroll
    for (int j = 0; j < J; j++) {
        float m = rxl[j] + rxr[j] + a0 * w0[j] + a1 * w1[j] + a2 * w2[j];
        m = (m > 0.0f) ? m : 0.2f * m;
        float cb = m * at[j];
        if (j < J / 2) l0 += cb; else l1 += cb;
    }
    #pragma unroll
    for (int off = 16; off; off >>= 1) {
        l0 += __shfl_xor_sync(0xFFFFFFFFu, l0, off);
        l1 += __shfl_xor_sync(0xFFFFFFFFu, l1, off);
    }
    float nm0 = fmaxf(m0, l0), nm1 = fmaxf(m1, l1);
    float sc0 = __expf(m0 - nm0), sc1 = __expf(m1 - nm1);
    float p0 = __expf(l0 - nm0), p1 = __expf(l1 - nm1);
    s0 = s0 * sc0 + p0;
    s1 = s1 * sc1 + p1;
    m0 = nm0; m1 = nm1;
    #pragma unroll
    for (int j = 0; j < J; j++) {
        float sc = (j < J / 2) ? sc0 : sc1;
        float p = (j < J / 2) ? p0 : p1;
        acc[j] = acc[j] * sc + p * rxl[j];
    }
}

template <int C, int U>
__global__ void k_gat(const int* __restrict__ rowptr,
                      const float4* __restrict__ eas,
                      const __half2* __restrict__ xlh, const float* __restrict__ xr,
                      const float* __restrict__ we, const float* __restrict__ att,
                      float* __restrict__ agg) {
    const int HC = 2 * C;
    const int J = HC / 32;
    int warp = (blockIdx.x * blockDim.x + threadIdx.x) >> 5;
    int lane = threadIdx.x & 31;
    if (warp >= NN) return;
    int beg = rowptr[warp];
    int d = rowptr[warp + 1] - beg;

    float rxr[J], w0[J], w1[J], w2[J], at[J], acc[J];
    #pragma unroll
    for (int j = 0; j < J; j++) {
        int col = lane + 32 * j;
        rxr[j] = xr[(size_t)warp * HC + col];
        w0[j] = we[col];
        w1[j] = we[HC + col];
        w2[j] = we[2 * HC + col];
        at[j] = att[col];
        acc[j] = 0.0f;
    }
    float m0 = -3.402823466e38f, m1 = -3.402823466e38f;
    float s0 = 0.0f, s1 = 0.0f;
    float as0 = 0.0f, as1 = 0.0f, as2 = 0.0f;

    int i = 0;
    if (U - 1 < d) {
        float4 e[U];
        #pragma unroll
        for (int q = 0; q < U; q++) e[q] = eas[beg + q];

        for (; i + U - 1 < d; ) {
            // issue this batch's gathers first (critical path)
            const __half2* xp[U];
            #pragma unroll
            for (int q = 0; q < U; q++)
                xp[q] = xlh + (size_t)__float_as_int(e[q].w) * C;
            float r[U][J];
            #pragma unroll
            for (int q = 0; q < U; q++)
                #pragma unroll
                for (int jj = 0; jj < J / 2; jj++) {
                    float2 f = __half22float2(xp[q][lane + 32 * jj]);
                    r[q][jj] = f.x;
                    r[q][jj + J / 2] = f.y;
                }
            // prefetch next batch's eas — overlaps with the math below
            float4 en[U];
            bool hn = (i + 2 * U - 1) < d;
            if (hn) {
                #pragma unroll
                for (int q = 0; q < U; q++) en[q] = eas[beg + i + U + q];
            }
            #pragma unroll
            for (int q = 0; q < U; q++) { as0 += e[q].x; as1 += e[q].y; as2 += e[q].z; }

            float l0[U], l1[U];
            #pragma unroll
            for (int q = 0; q < U; q++) { l0[q] = 0.0f; l1[q] = 0.0f; }
            #pragma unroll
            for (int j = 0; j < J; j++) {
                #pragma unroll
                for (int q = 0; q < U; q++) {
                    float m = r[q][j] + rxr[j] + e[q].x * w0[j] + e[q].y * w1[j] + e[q].z * w2[j];
                    m = (m > 0.0f) ? m : 0.2f * m;
                    float cb = m * at[j];
                    if (j < J / 2) l0[q] += cb; else l1[q] += cb;
                }
            }
            #pragma unroll
            for (int off = 16; off; off >>= 1) {
                #pragma unroll
                for (int q = 0; q < U; q++) {
                    l0[q] += __shfl_xor_sync(0xFFFFFFFFu, l0[q], off);
                    l1[q] += __shfl_xor_sync(0xFFFFFFFFu, l1[q], off);
                }
            }
            float nm0 = m0, nm1 = m1;
            #pragma unroll
            for (int q = 0; q < U; q++) {
                nm0 = fmaxf(nm0, l0[q]);
                nm1 = fmaxf(nm1, l1[q]);
            }
            float sc0 = __expf(m0 - nm0), sc1 = __expf(m1 - nm1);
            float p0[U], p1[U];
            float ps0 = 0.0f, ps1 = 0.0f;
            #pragma unroll
            for (int q = 0; q < U; q++) {
                p0[q] = __expf(l0[q] - nm0);
                p1[q] = __expf(l1[q] - nm1);
                ps0 += p0[q]; ps1 += p1[q];
            }
            s0 = s0 * sc0 + ps0;
            s1 = s1 * sc1 + ps1;
            m0 = nm0; m1 = nm1;
            #pragma unroll
            for (int j = 0; j < J; j++) {
                float sc = (j < J / 2) ? sc0 : sc1;
                float a = acc[j] * sc;
                #pragma unroll
                for (int q = 0; q < U; q++) {
                    float p = (j < J / 2) ? p0[q] : p1[q];
                    a += p * r[q][j];
                }
                acc[j] = a;
            }
            i += U;
            if (hn) {
                #pragma unroll
                for (int q = 0; q < U; q++) e[q] = en[q];
            }
        }
    }
    for (; i < d; i++) {   // remainder
        float4 e = eas[beg + i];
        as0 += e.x; as1 += e.y; as2 += e.z;
        gat_one<J>(xlh + (size_t)__float_as_int(e.w) * C, e.x, e.y, e.z, lane,
                   rxr, w0, w1, w2, at, acc, m0, m1, s0, s1);
    }
    {   // self-loop with mean edge attrs
        float inv = 1.0f / fmaxf((float)d, 1.0f);
        gat_one<J>(xlh + (size_t)warp * C, as0 * inv, as1 * inv, as2 * inv, lane,
                   rxr, w0, w1, w2, at, acc, m0, m1, s0, s1);
    }
    float inv0 = 0.5f / (s0 + 1e-16f);
    float inv1 = 0.5f / (s1 + 1e-16f);
    #pragma unroll
    for (int j = 0; j < J / 2; j++)
        agg[(size_t)warp * C + lane + 32 * j] = acc[j] * inv0 + acc[j + J / 2] * inv1;
}

// ---------------- batchnorm stats ----------------
template <int C>
__global__ void k_bnstats(const float* __restrict__ agg, const float* __restrict__ bias,
                          double* bns) {
    int tid = blockIdx.x * blockDim.x + threadIdx.x;
    int total = gridDim.x * blockDim.x;
    int c = tid % C;
    int slot = tid / C;
    int tpc = total / C;
    float b = bias[c];
    float s = 0.0f, q = 0.0f;
    for (int n = slot; n < NN; n += tpc) {
        float v = agg[(size_t)n * C + c] + b;
        s += v;
        q += v * v;
    }
    atomicAdd(&bns[c], (double)s);
    atomicAdd(&bns[C + c], (double)q);
}

// ---------------- BN+ELU + mean pool (block per graph, 4 row-streams) ----------------
__global__ void k_pool(const float* __restrict__ agg, const float* __restrict__ bias,
                       const double* __restrict__ bns,
                       const float* __restrict__ g, const float* __restrict__ be,
                       const int* __restrict__ gstart, float* __restrict__ pool) {
    __shared__ float red[4][64];
    int gb = blockIdx.x;
    int c = threadIdx.x & 63;
    int rr = threadIdx.x >> 6;   // 0..3
    int s = gstart[gb], e = gstart[gb + 1];
    double mu = bns[c] / (double)NN;
    double var = bns[64 + c] / (double)NN - mu * mu;
    float rs = rsqrtf((float)var + 1e-5f) * g[c];
    float sh = (bias[c] - (float)mu) * rs + be[c];
    float sum = 0.0f;
    for (int n = s + rr; n < e; n += 4) {
        float y = agg[(size_t)n * 64 + c] * rs + sh;
        sum += (y > 0.0f) ? y : expm1f(y);
    }
    red[rr][c] = sum;
    __syncthreads();
    if (rr == 0) {
        float t = red[0][c] + red[1][c] + red[2][c] + red[3][c];
        pool[gb * 64 + c] = t / fmaxf((float)(e - s), 1.0f);
    }
}

// ---------------- head ----------------
__global__ void k_head1(const float* __restrict__ pool,
                        const float* __restrict__ fc1w, const float* __restrict__ fc1b,
                        float* z, double* bns3) {
    __shared__ float sp[64];
    int g = blockIdx.x, t = threadIdx.x;
    if (t < 64) sp[t] = pool[g * 64 + t];
    __syncthreads();
    if (t < 32) {
        float acc = fc1b[t];
        #pragma unroll
        for (int k = 0; k < 64; k++) acc += sp[k] * fc1w[k * 32 + t];
        z[g * 32 + t] = acc;
        atomicAdd(&bns3[t], (double)acc);
        atomicAdd(&bns3[32 + t], (double)(acc * acc));
    }
}

__global__ void k_head2(const float* __restrict__ z, const double* __restrict__ bns3,
                        const float* __restrict__ g3, const float* __restrict__ be3,
                        const float* __restrict__ fc2w, const float* __restrict__ fc2b,
                        float* out) {
    int warp = (blockIdx.x * blockDim.x + threadIdx.x) >> 5;
    int lane = threadIdx.x & 31;
    if (warp >= NG) return;
    double mu = bns3[lane] / (double)NG;
    double var = bns3[32 + lane] / (double)NG - mu * mu;
    float zl = z[warp * 32 + lane];
    float y = (zl - (float)mu) * rsqrtf((float)var + 1e-5f) * g3[lane] + be3[lane];
    y = (y > 0.0f) ? y : expm1f(y);
    float p = y * fc2w[lane];
    #pragma unroll
    for (int off = 16; off; off >>= 1) p += __shfl_xor_sync(0xFFFFFFFFu, p, off);
    if (lane == 0) out[warp] = 1.0f / (1.0f + expf(-(p + fc2b[0])));
}

// ---------------- launch ----------------
extern "C" void kernel_launch(void* const* d_in, const int* in_sizes, int n_in,
                              void* d_out, int out_size) {
    const float* x     = (const float*)d_in[0];
    const float* ea    = (const float*)d_in[1];
    const float* w1l   = (const float*)d_in[2];
    const float* b1l   = (const float*)d_in[3];
    const float* w1r   = (const float*)d_in[4];
    const float* b1r   = (const float*)d_in[5];
    const float* w1e   = (const float*)d_in[6];
    const float* att1  = (const float*)d_in[7];
    const float* bias1 = (const float*)d_in[8];
    const float* g1    = (const float*)d_in[9];
    const float* be1   = (const float*)d_in[10];
    const float* w2l   = (const float*)d_in[11];
    const float* b2l   = (const float*)d_in[12];
    const float* w2r   = (const float*)d_in[13];
    const float* b2r   = (const float*)d_in[14];
    const float* w2e   = (const float*)d_in[15];
    const float* att2  = (const float*)d_in[16];
    const float* bias2 = (const float*)d_in[17];
    const float* g2    = (const float*)d_in[18];
    const float* be2   = (const float*)d_in[19];
    const float* fc1w  = (const float*)d_in[20];
    const float* fc1b  = (const float*)d_in[21];
    const float* g3    = (const float*)d_in[22];
    const float* be3   = (const float*)d_in[23];
    const float* fc2w  = (const float*)d_in[24];
    const float* fc2b  = (const float*)d_in[25];
    const int*   ei    = (const int*)d_in[26];
    const int*   batch = (const int*)d_in[27];
    float* out = (float*)d_out;

    float *xl, *xr, *agg, *pool, *zbuf;
    double *bns, *bns3;
    int *cnt, *rowptr, *cursor, *bsum, *gstart;
    float4 *eas;
    cudaGetSymbolAddress((void**)&xl, g_xl);
    cudaGetSymbolAddress((void**)&xr, g_xr);
    cudaGetSymbolAddress((void**)&agg, g_agg);
    cudaGetSymbolAddress((void**)&pool, g_pool);
    cudaGetSymbolAddress((void**)&zbuf, g_z);
    cudaGetSymbolAddress((void**)&bns, g_bns);
    cudaGetSymbolAddress((void**)&bns3, g_bns3);
    cudaGetSymbolAddress((void**)&cnt, g_cnt);
    cudaGetSymbolAddress((void**)&rowptr, g_rowptr);
    cudaGetSymbolAddress((void**)&cursor, g_cursor);
    cudaGetSymbolAddress((void**)&bsum, g_bsum);
    cudaGetSymbolAddress((void**)&eas, g_eas);
    cudaGetSymbolAddress((void**)&gstart, g_gstart);
    __half* xlh = (__half*)xl;

    const int gatBlocks = (NN * 32 + 255) / 256;  // warp per node
    dim3 linGrid(NN / 64, 2);

    // --- CSR build + graph bounds ---
    cudaMemsetAsync(cnt, 0, NN * sizeof(int));
    k_count<<<(NE + 255) / 256, 256>>>(ei, cnt);
    k_scan1<<<128, 1024>>>(cnt, rowptr, bsum);
    k_scan2<<<1, 128>>>(bsum);
    k_scan3<<<(NN + 256) / 256, 256>>>(rowptr, bsum, cursor);
    k_scatter<<<(NE + 255) / 256, 256>>>(ei, ea, cursor, eas);
    k_bounds<<<3, 256>>>(batch, gstart);

    // --- layer 1 ---
    k_lin<64, 64, 4, false><<<linGrid, 256>>>(x, w1l, b1l, w1r, b1r,
                                              nullptr, nullptr, nullptr, nullptr, xlh, xr);
    k_gat<32, 4><<<gatBlocks, 256>>>(rowptr, eas, (const __half2*)xlh, xr, w1e, att1, agg);
    cudaMemsetAsync(bns, 0, 128 * sizeof(double));
    k_bnstats<32><<<512, 256>>>(agg, bias1, bns);

    // --- layer 2 (BN+ELU of layer-1 fused into the linear's input load) ---
    k_lin<32, 128, 8, true><<<linGrid, 256>>>(agg, w2l, b2l, w2r, b2r,
                                              bias1, bns, g1, be1, xlh, xr);
    k_gat<64, 2><<<gatBlocks, 256>>>(rowptr, eas, (const __half2*)xlh, xr, w2e, att2, agg);
    cudaMemsetAsync(bns, 0, 128 * sizeof(double));
    k_bnstats<64><<<512, 256>>>(agg, bias2, bns);

    // --- pool + head (atomic-free) ---
    k_pool<<<NG, 256>>>(agg, bias2, bns, g2, be2, gstart, pool);
    cudaMemsetAsync(bns3, 0, 64 * sizeof(double));
    k_head1<<<NG, 64>>>(pool, fc1w, fc1b, zbuf, bns3);
    k_head2<<<(NG * 32 + 255) / 256, 256>>>(zbuf, bns3, g3, be3, fc2w, fc2b, out);
}

// round 17
// speedup vs baseline: 1.2035x; 1.2035x over previous
#include <cuda_runtime.h>
#include <cuda_fp16.h>
#include <math.h>

#define NN 131072
#define NE 2097152
#define NG 512

// ---------------- scratch (device globals; no runtime allocation) ----------------
__device__ float  g_xl[NN * 128];     // reinterpreted as __half (lane-packed layout)
__device__ float  g_xr[NN * 128];
__device__ float  g_agg[NN * 64];
__device__ float  g_pool[NG * 64];
__device__ float  g_z[NG * 32];
__device__ double g_bns[128];
__device__ double g_bns3[64];
__device__ int    g_rowptr[NN + 1];
__device__ int    g_cnt[NN];
__device__ int    g_cursor[NN];
__device__ float4 g_eas[NE];     // (a0,a1,a2, bitcast src)
__device__ int    g_bsum[128];
__device__ int    g_gstart[NG + 1];

// ---------------- degree count ----------------
__global__ void k_count(const int* __restrict__ ei, int* cnt) {
    int e = blockIdx.x * blockDim.x + threadIdx.x;
    if (e >= NE) return;
    atomicAdd(&cnt[ei[NE + e]], 1);
}

// ---------------- CSR scan (3-phase) ----------------
__global__ void k_scan1(const int* __restrict__ cnt, int* rowptr, int* bsum) {
    __shared__ int sh[1024];
    int t = threadIdx.x;
    int i = blockIdx.x * 1024 + t;
    int v = cnt[i];
    sh[t] = v;
    __syncthreads();
    for (int off = 1; off < 1024; off <<= 1) {
        int u = (t >= off) ? sh[t - off] : 0;
        __syncthreads();
        sh[t] += u;
        __syncthreads();
    }
    rowptr[i] = sh[t] - v;   // exclusive
    if (t == 1023) bsum[blockIdx.x] = sh[1023];
}

__global__ void k_scan2(int* bsum) {
    __shared__ int sh[128];
    int t = threadIdx.x;
    int orig = bsum[t];
    sh[t] = orig;
    __syncthreads();
    for (int off = 1; off < 128; off <<= 1) {
        int u = (t >= off) ? sh[t - off] : 0;
        __syncthreads();
        sh[t] += u;
        __syncthreads();
    }
    bsum[t] = sh[t] - orig;  // exclusive
}

__global__ void k_scan3(int* rowptr, const int* __restrict__ bsum, int* cursor) {
    int i = blockIdx.x * blockDim.x + threadIdx.x;
    if (i >= NN) {
        if (i == NN) rowptr[NN] = NE;   // sentinel
        return;
    }
    int r = rowptr[i] + bsum[i >> 10];
    rowptr[i] = r;
    cursor[i] = r;
}

__global__ void k_scatter(const int* __restrict__ ei, const float* __restrict__ ea,
                          int* cursor, float4* eas) {
    int e = blockIdx.x * blockDim.x + threadIdx.x;
    if (e >= NE) return;
    int dst = ei[NE + e];
    int pos = atomicAdd(&cursor[dst], 1);
    eas[pos] = make_float4(ea[e * 3 + 0], ea[e * 3 + 1], ea[e * 3 + 2],
                           __int_as_float(ei[e]));
}

// ---------------- graph boundaries (batch is sorted) ----------------
__global__ void k_bounds(const int* __restrict__ batch, int* gstart) {
    int g = blockIdx.x * blockDim.x + threadIdx.x;
    if (g > NG) return;
    int lo = 0, hi = NN;
    while (lo < hi) {
        int mid = (lo + hi) >> 1;
        if (batch[mid] < g) lo = mid + 1; else hi = mid;
    }
    gstart[g] = lo;
}

// ---------------- register-tiled node linear ----------------
// xl output (blockIdx.y==0) stored fp16 lane-packed:
//   col -> h = col/C, c = col%C, pc = (c&31)*(BN/32) + (c>>5)*2 + h
// so each lane's BN/32 halves are contiguous (one 4B/8B load in k_gat).
template <int K, int BN, int TN, bool BNELU>
__global__ void k_lin(const float* __restrict__ in,
                      const float* __restrict__ wl, const float* __restrict__ bl,
                      const float* __restrict__ wr, const float* __restrict__ br,
                      const float* __restrict__ bias, const double* __restrict__ bns,
                      const float* __restrict__ gam, const float* __restrict__ bet,
                      __half* __restrict__ xlh, float* __restrict__ xr) {
    const int BM = 64, TM = 4;
    const int C = BN / 2;
    __shared__ float sx[BM][K + 1];
    __shared__ float sw[K * BN];
    __shared__ float ss[K], st[K];
    const float* w  = blockIdx.y ? wr : wl;
    const float* bb = blockIdx.y ? br : bl;
    int tid = threadIdx.x;

    for (int i = tid; i < K * BN; i += 256) sw[i] = w[i];
    if (BNELU && tid < K) {
        double mu = bns[tid] / (double)NN;
        double var = bns[K + tid] / (double)NN - mu * mu;
        float rs = rsqrtf((float)var + 1e-5f);
        ss[tid] = rs * gam[tid];
        st[tid] = (bias[tid] - (float)mu) * rs * gam[tid] + bet[tid];
    }
    int node0 = blockIdx.x * BM;
    for (int i = tid; i < BM * K; i += 256) {
        int r = i / K, c = i % K;
        sx[r][c] = in[(size_t)(node0 + r) * K + c];
    }
    __syncthreads();
    if (BNELU) {
        for (int i = tid; i < BM * K; i += 256) {
            int r = i / K, c = i % K;
            float v = sx[r][c] * ss[c] + st[c];
            sx[r][c] = (v > 0.0f) ? v : expm1f(v);
        }
        __syncthreads();
    }

    int ty = tid / 16, tx = tid % 16;
    int nb = ty * TM, cb = tx * TN;
    float acc[TM][TN];
    #pragma unroll
    for (int m = 0; m < TM; m++)
        #pragma unroll
        for (int n = 0; n < TN; n++) acc[m][n] = bb[cb + n];

    #pragma unroll 4
    for (int k = 0; k < K; k++) {
        float a[TM], b[TN];
        #pragma unroll
        for (int m = 0; m < TM; m++) a[m] = sx[nb + m][k];
        #pragma unroll
        for (int n = 0; n < TN; n += 4) {
            float4 v = *(const float4*)&sw[k * BN + cb + n];
            b[n] = v.x; b[n + 1] = v.y; b[n + 2] = v.z; b[n + 3] = v.w;
        }
        #pragma unroll
        for (int m = 0; m < TM; m++)
            #pragma unroll
            for (int n = 0; n < TN; n++) acc[m][n] += a[m] * b[n];
    }
    if (blockIdx.y == 0) {
        // xl: fp16 lane-packed stores
        #pragma unroll
        for (int m = 0; m < TM; m++)
            #pragma unroll
            for (int n = 0; n < TN; n++) {
                int col = cb + n;
                int h = (col < C) ? 0 : 1;
                int c = col - h * C;
                int pc = (c & 31) * (BN / 32) + (c >> 5) * 2 + h;
                xlh[(size_t)(node0 + nb + m) * BN + pc] = __float2half(acc[m][n]);
            }
    } else {
        #pragma unroll
        for (int m = 0; m < TM; m++)
            #pragma unroll
            for (int n = 0; n < TN; n += 4) {
                float4 v = make_float4(acc[m][n], acc[m][n + 1], acc[m][n + 2], acc[m][n + 3]);
                *(float4*)&xr[(size_t)(node0 + nb + m) * BN + cb + n] = v;
            }
    }
}

// ---------------- lane-packed xl row loader ----------------
// J==2 (layer 1): one 4B load.  J==4 (layer 2): one 8B load.
template <int J>
struct XlLoader;

template <>
struct XlLoader<2> {
    static __device__ __forceinline__ void load(const __half* __restrict__ row,
                                                int lane, float* rxl) {
        __half2 v = ((const __half2*)row)[lane];
        float2 f = __half22float2(v);
        rxl[0] = f.x;   // j0: head0, c=lane
        rxl[1] = f.y;   // j1: head1, c=lane
    }
};

template <>
struct XlLoader<4> {
    static __device__ __forceinline__ void load(const __half* __restrict__ row,
                                                int lane, float* rxl) {
        uint2 v = ((const uint2*)row)[lane];
        float2 a = __half22float2(*(const __half2*)&v.x);  // (c=lane  h0, c=lane  h1)
        float2 b = __half22float2(*(const __half2*)&v.y);  // (c=lane+32 h0, c=lane+32 h1)
        rxl[0] = a.x;   // j0: head0 c=lane
        rxl[1] = b.x;   // j1: head0 c=lane+32
        rxl[2] = a.y;   // j2: head1 c=lane
        rxl[3] = b.y;   // j3: head1 c=lane+32
    }
};

// ---------------- fused GATv2 (lane-packed xl gathers, templated edge unroll) ----------------
template <int J>
__device__ __forceinline__ void gat_one(const __half* __restrict__ xls,
                                        float a0, float a1, float a2, int lane,
                                        const float* rxr, const float* w0,
                                        const float* w1, const float* w2,
                                        const float* at, float* acc,
                                        float& m0, float& m1, float& s0, float& s1) {
    float rxl[J];
    XlLoader<J>::load(xls, lane, rxl);
    float l0 = 0.0f, l1 = 0.0f;
    #pragma unroll
    for (int j = 0; j < J; j++) {
        float m = rxl[j] + rxr[j] + a0 * w0[j] + a1 * w1[j] + a2 * w2[j];
        m = (m > 0.0f) ? m : 0.2f * m;
        float cb = m * at[j];
        if (j < J / 2) l0 += cb; else l1 += cb;
    }
    #pragma unroll
    for (int off = 16; off; off >>= 1) {
        l0 += __shfl_xor_sync(0xFFFFFFFFu, l0, off);
        l1 += __shfl_xor_sync(0xFFFFFFFFu, l1, off);
    }
    float nm0 = fmaxf(m0, l0), nm1 = fmaxf(m1, l1);
    float sc0 = __expf(m0 - nm0), sc1 = __expf(m1 - nm1);
    float p0 = __expf(l0 - nm0), p1 = __expf(l1 - nm1);
    s0 = s0 * sc0 + p0;
    s1 = s1 * sc1 + p1;
    m0 = nm0; m1 = nm1;
    #pragma unroll
    for (int j = 0; j < J; j++) {
        float sc = (j < J / 2) ? sc0 : sc1;
        float p = (j < J / 2) ? p0 : p1;
        acc[j] = acc[j] * sc + p * rxl[j];
    }
}

// NOTE on index mapping: j enumerates (head, half) as
//   j0 = (h0, c=lane), j1 = (h0, c=lane+32) [J=4 only], then head1 mirrors.
// rxr/w/at must be loaded with the same mapping (see col computation below).
template <int C, int U>
__global__ void k_gat(const int* __restrict__ rowptr,
                      const float4* __restrict__ eas,
                      const __half* __restrict__ xlh, const float* __restrict__ xr,
                      const float* __restrict__ we, const float* __restrict__ att,
                      float* __restrict__ agg) {
    const int HC = 2 * C;
    const int J = HC / 32;
    const int JH = J / 2;          // halves per head
    int warp = (blockIdx.x * blockDim.x + threadIdx.x) >> 5;
    int lane = threadIdx.x & 31;
    if (warp >= NN) return;
    int beg = rowptr[warp];
    int d = rowptr[warp + 1] - beg;

    float rxr[J], w0[J], w1[J], w2[J], at[J], acc[J];
    #pragma unroll
    for (int j = 0; j < J; j++) {
        // j -> (head = j/JH, c = lane + 32*(j%JH)) -> original col = head*C + c
        int col = (j / JH) * C + lane + 32 * (j % JH);
        rxr[j] = xr[(size_t)warp * HC + col];
        w0[j] = we[col];
        w1[j] = we[HC + col];
        w2[j] = we[2 * HC + col];
        at[j] = att[col];
        acc[j] = 0.0f;
    }
    float m0 = -3.402823466e38f, m1 = -3.402823466e38f;
    float s0 = 0.0f, s1 = 0.0f;
    float as0 = 0.0f, as1 = 0.0f, as2 = 0.0f;

    int i = 0;
    for (; i + U - 1 < d; i += U) {
        float4 e[U];
        const __half* xp[U];
        #pragma unroll
        for (int q = 0; q < U; q++) {
            e[q] = eas[beg + i + q];
            as0 += e[q].x; as1 += e[q].y; as2 += e[q].z;
            xp[q] = xlh + (size_t)__float_as_int(e[q].w) * HC;
        }
        float r[U][J];
        #pragma unroll
        for (int q = 0; q < U; q++)
            XlLoader<J>::load(xp[q], lane, r[q]);
        float l0[U], l1[U];
        #pragma unroll
        for (int q = 0; q < U; q++) { l0[q] = 0.0f; l1[q] = 0.0f; }
        #pragma unroll
        for (int j = 0; j < J; j++) {
            #pragma unroll
            for (int q = 0; q < U; q++) {
                float m = r[q][j] + rxr[j] + e[q].x * w0[j] + e[q].y * w1[j] + e[q].z * w2[j];
                m = (m > 0.0f) ? m : 0.2f * m;
                float cb = m * at[j];
                if (j < J / 2) l0[q] += cb; else l1[q] += cb;
            }
        }
        #pragma unroll
        for (int off = 16; off; off >>= 1) {
            #pragma unroll
            for (int q = 0; q < U; q++) {
                l0[q] += __shfl_xor_sync(0xFFFFFFFFu, l0[q], off);
                l1[q] += __shfl_xor_sync(0xFFFFFFFFu, l1[q], off);
            }
        }
        float nm0 = m0, nm1 = m1;
        #pragma unroll
        for (int q = 0; q < U; q++) {
            nm0 = fmaxf(nm0, l0[q]);
            nm1 = fmaxf(nm1, l1[q]);
        }
        float sc0 = __expf(m0 - nm0), sc1 = __expf(m1 - nm1);
        float p0[U], p1[U];
        float ps0 = 0.0f, ps1 = 0.0f;
        #pragma unroll
        for (int q = 0; q < U; q++) {
            p0[q] = __expf(l0[q] - nm0);
            p1[q] = __expf(l1[q] - nm1);
            ps0 += p0[q]; ps1 += p1[q];
        }
        s0 = s0 * sc0 + ps0;
        s1 = s1 * sc1 + ps1;
        m0 = nm0; m1 = nm1;
        #pragma unroll
        for (int j = 0; j < J; j++) {
            float sc = (j < J / 2) ? sc0 : sc1;
            float a = acc[j] * sc;
            #pragma unroll
            for (int q = 0; q < U; q++) {
                float p = (j < J / 2) ? p0[q] : p1[q];
                a += p * r[q][j];
            }
            acc[j] = a;
        }
    }
    for (; i < d; i++) {   // remainder
        float4 e = eas[beg + i];
        as0 += e.x; as1 += e.y; as2 += e.z;
        gat_one<J>(xlh + (size_t)__float_as_int(e.w) * HC, e.x, e.y, e.z, lane,
                   rxr, w0, w1, w2, at, acc, m0, m1, s0, s1);
    }
    {   // self-loop with mean edge attrs
        float inv = 1.0f / fmaxf((float)d, 1.0f);
        gat_one<J>(xlh + (size_t)warp * HC, as0 * inv, as1 * inv, as2 * inv, lane,
                   rxr, w0, w1, w2, at, acc, m0, m1, s0, s1);
    }
    // head-mean: output channel c gets (head0[c] + head1[c]) / 2 with per-head softmax norm.
    // j (head0) pairs with j+J/2 (head1) at the SAME c = lane + 32*(j%JH).
    float inv0 = 0.5f / (s0 + 1e-16f);
    float inv1 = 0.5f / (s1 + 1e-16f);
    #pragma unroll
    for (int j = 0; j < J / 2; j++)
        agg[(size_t)warp * C + lane + 32 * j] = acc[j] * inv0 + acc[j + J / 2] * inv1;
}

// ---------------- batchnorm stats ----------------
template <int C>
__global__ void k_bnstats(const float* __restrict__ agg, const float* __restrict__ bias,
                          double* bns) {
    int tid = blockIdx.x * blockDim.x + threadIdx.x;
    int total = gridDim.x * blockDim.x;
    int c = tid % C;
    int slot = tid / C;
    int tpc = total / C;
    float b = bias[c];
    float s = 0.0f, q = 0.0f;
    for (int n = slot; n < NN; n += tpc) {
        float v = agg[(size_t)n * C + c] + b;
        s += v;
        q += v * v;
    }
    atomicAdd(&bns[c], (double)s);
    atomicAdd(&bns[C + c], (double)q);
}

// ---------------- BN+ELU + mean pool (block per graph, 4 row-streams) ----------------
__global__ void k_pool(const float* __restrict__ agg, const float* __restrict__ bias,
                       const double* __restrict__ bns,
                       const float* __restrict__ g, const float* __restrict__ be,
                       const int* __restrict__ gstart, float* __restrict__ pool) {
    __shared__ float red[4][64];
    int gb = blockIdx.x;
    int c = threadIdx.x & 63;
    int rr = threadIdx.x >> 6;   // 0..3
    int s = gstart[gb], e = gstart[gb + 1];
    double mu = bns[c] / (double)NN;
    double var = bns[64 + c] / (double)NN - mu * mu;
    float rs = rsqrtf((float)var + 1e-5f) * g[c];
    float sh = (bias[c] - (float)mu) * rs + be[c];
    float sum = 0.0f;
    for (int n = s + rr; n < e; n += 4) {
        float y = agg[(size_t)n * 64 + c] * rs + sh;
        sum += (y > 0.0f) ? y : expm1f(y);
    }
    red[rr][c] = sum;
    __syncthreads();
    if (rr == 0) {
        float t = red[0][c] + red[1][c] + red[2][c] + red[3][c];
        pool[gb * 64 + c] = t / fmaxf((float)(e - s), 1.0f);
    }
}

// ---------------- head ----------------
__global__ void k_head1(const float* __restrict__ pool,
                        const float* __restrict__ fc1w, const float* __restrict__ fc1b,
                        float* z, double* bns3) {
    __shared__ float sp[64];
    int g = blockIdx.x, t = threadIdx.x;
    if (t < 64) sp[t] = pool[g * 64 + t];
    __syncthreads();
    if (t < 32) {
        float acc = fc1b[t];
        #pragma unroll
        for (int k = 0; k < 64; k++) acc += sp[k] * fc1w[k * 32 + t];
        z[g * 32 + t] = acc;
        atomicAdd(&bns3[t], (double)acc);
        atomicAdd(&bns3[32 + t], (double)(acc * acc));
    }
}

__global__ void k_head2(const float* __restrict__ z, const double* __restrict__ bns3,
                        const float* __restrict__ g3, const float* __restrict__ be3,
                        const float* __restrict__ fc2w, const float* __restrict__ fc2b,
                        float* out) {
    int warp = (blockIdx.x * blockDim.x + threadIdx.x) >> 5;
    int lane = threadIdx.x & 31;
    if (warp >= NG) return;
    double mu = bns3[lane] / (double)NG;
    double var = bns3[32 + lane] / (double)NG - mu * mu;
    float zl = z[warp * 32 + lane];
    float y = (zl - (float)mu) * rsqrtf((float)var + 1e-5f) * g3[lane] + be3[lane];
    y = (y > 0.0f) ? y : expm1f(y);
    float p = y * fc2w[lane];
    #pragma unroll
    for (int off = 16; off; off >>= 1) p += __shfl_xor_sync(0xFFFFFFFFu, p, off);
    if (lane == 0) out[warp] = 1.0f / (1.0f + expf(-(p + fc2b[0])));
}

// ---------------- launch ----------------
extern "C" void kernel_launch(void* const* d_in, const int* in_sizes, int n_in,
                              void* d_out, int out_size) {
    const float* x     = (const float*)d_in[0];
    const float* ea    = (const float*)d_in[1];
    const float* w1l   = (const float*)d_in[2];
    const float* b1l   = (const float*)d_in[3];
    const float* w1r   = (const float*)d_in[4];
    const float* b1r   = (const float*)d_in[5];
    const float* w1e   = (const float*)d_in[6];
    const float* att1  = (const float*)d_in[7];
    const float* bias1 = (const float*)d_in[8];
    const float* g1    = (const float*)d_in[9];
    const float* be1   = (const float*)d_in[10];
    const float* w2l   = (const float*)d_in[11];
    const float* b2l   = (const float*)d_in[12];
    const float* w2r   = (const float*)d_in[13];
    const float* b2r   = (const float*)d_in[14];
    const float* w2e   = (const float*)d_in[15];
    const float* att2  = (const float*)d_in[16];
    const float* bias2 = (const float*)d_in[17];
    const float* g2    = (const float*)d_in[18];
    const float* be2   = (const float*)d_in[19];
    const float* fc1w  = (const float*)d_in[20];
    const float* fc1b  = (const float*)d_in[21];
    const float* g3    = (const float*)d_in[22];
    const float* be3   = (const float*)d_in[23];
    const float* fc2w  = (const float*)d_in[24];
    const float* fc2b  = (const float*)d_in[25];
    const int*   ei    = (const int*)d_in[26];
    const int*   batch = (const int*)d_in[27];
    float* out = (float*)d_out;

    float *xl, *xr, *agg, *pool, *zbuf;
    double *bns, *bns3;
    int *cnt, *rowptr, *cursor, *bsum, *gstart;
    float4 *eas;
    cudaGetSymbolAddress((void**)&xl, g_xl);
    cudaGetSymbolAddress((void**)&xr, g_xr);
    cudaGetSymbolAddress((void**)&agg, g_agg);
    cudaGetSymbolAddress((void**)&pool, g_pool);
    cudaGetSymbolAddress((void**)&zbuf, g_z);
    cudaGetSymbolAddress((void**)&bns, g_bns);
    cudaGetSymbolAddress((void**)&bns3, g_bns3);
    cudaGetSymbolAddress((void**)&cnt, g_cnt);
    cudaGetSymbolAddress((void**)&rowptr, g_rowptr);
    cudaGetSymbolAddress((void**)&cursor, g_cursor);
    cudaGetSymbolAddress((void**)&bsum, g_bsum);
    cudaGetSymbolAddress((void**)&eas, g_eas);
    cudaGetSymbolAddress((void**)&gstart, g_gstart);
    __half* xlh = (__half*)xl;

    const int gatBlocks = (NN * 32 + 255) / 256;  // warp per node
    dim3 linGrid(NN / 64, 2);

    // --- CSR build + graph bounds ---
    cudaMemsetAsync(cnt, 0, NN * sizeof(int));
    k_count<<<(NE + 255) / 256, 256>>>(ei, cnt);
    k_scan1<<<128, 1024>>>(cnt, rowptr, bsum);
    k_scan2<<<1, 128>>>(bsum);
    k_scan3<<<(NN + 256) / 256, 256>>>(rowptr, bsum, cursor);
    k_scatter<<<(NE + 255) / 256, 256>>>(ei, ea, cursor, eas);
    k_bounds<<<3, 256>>>(batch, gstart);

    // --- layer 1 ---
    k_lin<64, 64, 4, false><<<linGrid, 256>>>(x, w1l, b1l, w1r, b1r,
                                              nullptr, nullptr, nullptr, nullptr, xlh, xr);
    k_gat<32, 4><<<gatBlocks, 256>>>(rowptr, eas, xlh, xr, w1e, att1, agg);
    cudaMemsetAsync(bns, 0, 128 * sizeof(double));
    k_bnstats<32><<<512, 256>>>(agg, bias1, bns);

    // --- layer 2 (BN+ELU of layer-1 fused into the linear's input load) ---
    k_lin<32, 128, 8, true><<<linGrid, 256>>>(agg, w2l, b2l, w2r, b2r,
                                              bias1, bns, g1, be1, xlh, xr);
    k_gat<64, 2><<<gatBlocks, 256>>>(rowptr, eas, xlh, xr, w2e, att2, agg);
    cudaMemsetAsync(bns, 0, 128 * sizeof(double));
    k_bnstats<64><<<512, 256>>>(agg, bias2, bns);

    // --- pool + head (atomic-free) ---
    k_pool<<<NG, 256>>>(agg, bias2, bns, g2, be2, gstart, pool);
    cudaMemsetAsync(bns3, 0, 64 * sizeof(double));
    k_head1<<<NG, 64>>>(pool, fc1w, fc1b, zbuf, bns3);
    k_head2<<<(NG * 32 + 255) / 256, 256>>>(zbuf, bns3, g3, be3, fc2w, fc2b, out);
}